// round 5
// baseline (speedup 1.0000x reference)
#include <cuda_runtime.h>
#include <math_constants.h>

// ScalarDistanceDeepSet, single persistent kernel.
// g(s) (1->64->128 relu MLP) is piecewise-linear: 64 layer-1 breakpoints -> 65
// segments with per-(segment,feature) (a,c); per-feature relu crossings theta
// give 8384 sorted boundaries -> 8385 cells on which every feature is linear.
// Phases (grid barriers between): 0) tables + zero  1) per-pair cell histogram
// (branchless 14-step search, ILP-4, integer atomics)  2) per-(batch,segment)
// warp scans + range algebra -> fixed-point pooled atomics  3) head MLP.
// All cross-block accumulation is integer => deterministic.

#define NB    32
#define NN    256
#define P1    64
#define P2    128
#define R1    256
#define R2    128
#define OD    64
#define NSEG  65
#define NCELL 129
#define NSLOT (NSEG * NCELL)      // 8385
#define NBND  (NSLOT - 1)         // 8384
#define SCALE_F    67108864.0f    // 2^26  (per-pair s quantization)
#define INV_SCALE  (1.0 / 67108864.0)
#define PSCALE     4194304.0      // 2^22  (pooled partial quantization)
#define INV_PSCALE (1.0 / 4194304.0)
#define GRID_MAX  592
#define NTASK (NB * (NN / 4))     // 2048 hist tasks

__device__ float     g_bnd[NBND];
__device__ float     g_A[NSEG * P2];
__device__ float     g_Cc[NSEG * P2];
__device__ int2      g_range[NSEG * P2];
__device__ long long g_hs[NB * NSLOT];
__device__ int       g_hc[NB * NSLOT];
__device__ long long g_poolq[NB * P2];
__device__ unsigned int g_bar[4];      // monotonic barrier counters

union SmUnion {
    float sb[NBND];                                          // hist (33.5 KB)
    struct { long long ps[8][130]; int pc[8][130]; } pool;   // 12.5 KB
    struct { float w[P1], bb[P1], tk[P1], ts[P1], sth[P2];
             int rk[P1]; } setup;                            // 1.8 KB
    struct { float pooled[P2], r1[R1], r2[R2], part[256]; } head; // 3 KB
};

// Monotonic grid barrier: no reset needed across graph replays.
__device__ __forceinline__ void grid_barrier(unsigned int* ctr, unsigned int nb) {
    __syncthreads();
    if (threadIdx.x == 0) {
        __threadfence();                                   // release (+ L1 inval)
        unsigned int a = atomicAdd(ctr, 1u);
        unsigned int target = a - (a % nb) + nb;
        while (atomicAdd(ctr, 0u) < target) __nanosleep(64);
        __threadfence();                                   // acquire
    }
    __syncthreads();
}

__global__ void __launch_bounds__(256)
mega_kernel(const float* __restrict__ dm, const int* __restrict__ lengths,
            const float* __restrict__ W1, const float* __restrict__ b1,
            const float* __restrict__ W2, const float* __restrict__ b2,
            const float* __restrict__ W3, const float* __restrict__ b3,
            const float* __restrict__ W4, const float* __restrict__ b4,
            const float* __restrict__ W5, const float* __restrict__ b5,
            float* __restrict__ out, int nb) {
    __shared__ SmUnion sm;
    int tid = threadIdx.x;

    // ---------------- Phase 0: zero + tables ----------------
    {
        int stride = nb * 256, idx0 = blockIdx.x * 256 + tid;
        for (int i = idx0; i < NB * NSLOT; i += stride) g_hs[i] = 0;
        for (int i = idx0; i < NB * NSLOT; i += stride) g_hc[i] = 0;
        for (int i = idx0; i < NB * P2;   i += stride) g_poolq[i] = 0;
    }
    for (int m = blockIdx.x; m < NSEG; m += nb) {
        if (tid < P1) {
            float w = W1[tid], b = b1[tid];
            sm.setup.w[tid] = w; sm.setup.bb[tid] = b;
            sm.setup.tk[tid] = (w != 0.0f) ? (-b / w) : CUDART_INF_F;
        }
        __syncthreads();
        if (tid < P1) {
            float tkv = sm.setup.tk[tid];
            int r = 0;
            for (int kk = 0; kk < P1; kk++) {
                float tv = sm.setup.tk[kk];
                if (tv < tkv || (tv == tkv && kk < tid)) r++;
            }
            sm.setup.rk[tid] = r;
            sm.setup.ts[r] = tkv;
        }
        __syncthreads();
        if (tid < P2) {
            float a = 0.0f, c = b2[tid];
            for (int k = 0; k < P1; k++) {
                float w = sm.setup.w[k], b = sm.setup.bb[k];
                int r = sm.setup.rk[k];
                bool active = (w > 0.0f) ? (m > r)
                            : (w < 0.0f) ? (m <= r)
                            : (b > 0.0f);
                if (active) {
                    float w2 = W2[k * P2 + tid];
                    a = fmaf(w, w2, a);
                    c = fmaf(b, w2, c);
                }
            }
            int idx = m * P2 + tid;
            g_A[idx] = a; g_Cc[idx] = c;

            float lo_t = (m == 0)        ? -CUDART_INF_F : sm.setup.ts[m - 1];
            float hi_t = (m == NSEG - 1) ?  CUDART_INF_F : sm.setup.ts[m];
            float th;
            if (a != 0.0f) th = fminf(fmaxf(-c / a, lo_t), hi_t);
            else           th = lo_t;
            sm.setup.sth[tid] = th;
            __syncwarp();
            // (rank among 128 needs all sth; block-level sync below)
        }
        __syncthreads();
        if (tid < P2) {
            int idx = m * P2 + tid;
            float a = g_A[idx], c = g_Cc[idx];
            float th = sm.setup.sth[tid];
            int p = 0;
            for (int k = 0; k < P2; k++) {
                float tv = sm.setup.sth[k];
                if (tv < th || (tv == th && k < tid)) p++;
            }
            g_bnd[m * NCELL + p] = th;
            if (tid == 0 && m < NSEG - 1) g_bnd[m * NCELL + P2] = sm.setup.ts[m];
            int rlo, rhi;
            if (a > 0.0f)      { rlo = p + 1; rhi = NCELL; }
            else if (a < 0.0f) { rlo = 0;     rhi = p + 1; }
            else               { rlo = 0;     rhi = (c > 0.0f) ? NCELL : 0; }
            g_range[idx] = make_int2(rlo, rhi);
        }
        __syncthreads();
    }
    grid_barrier(&g_bar[0], (unsigned)nb);

    // ---------------- Phase 1: histogram ----------------
    for (int i = tid; i < NBND; i += 256) sm.sb[i] = g_bnd[i];
    __syncthreads();
    for (int task = blockIdx.x; task < NTASK; task += nb) {
        int b  = task & 31;
        int i0 = (task >> 5) << 2;
        int L  = __ldg(lengths + b);
        if (i0 >= L - 1) continue;

        const float* rowp = dm + ((size_t)b << 16) + ((size_t)i0 << 8) + tid;
        float s[4]; int n[4], pos[4];
        #pragma unroll
        for (int r = 0; r < 4; r++) {
            int i = i0 + r;
            bool valid = (i < L - 1) && (tid > i) && (tid < L);
            s[r]   = valid ? rowp[r << 8] : 0.0f;
            pos[r] = 0;
            n[r]   = valid ? NBND : 0;
        }
        #pragma unroll
        for (int it = 0; it < 14; it++) {
            #pragma unroll
            for (int r = 0; r < 4; r++) {
                if (n[r] > 0) {
                    int half = n[r] >> 1;
                    int mid  = pos[r] + half;
                    if (sm.sb[mid] < s[r]) { pos[r] = mid + 1; n[r] -= half + 1; }
                    else                   { n[r] = half; }
                }
            }
        }
        unsigned long long* hsb = (unsigned long long*)g_hs + (size_t)b * NSLOT;
        int* hcb = g_hc + (size_t)b * NSLOT;
        #pragma unroll
        for (int r = 0; r < 4; r++) {
            int i = i0 + r;
            bool valid = (i < L - 1) && (tid > i) && (tid < L);
            if (valid) {
                long long q = llrintf(s[r] * SCALE_F);
                atomicAdd(&hsb[pos[r]], (unsigned long long)q);
                atomicAdd(&hcb[pos[r]], 1);
            }
        }
    }
    grid_barrier(&g_bar[1], (unsigned)nb);

    // ---------------- Phase 2: pooled (warp per (b,m) unit) ----------------
    {
        int warp = tid >> 5, lane = tid & 31;
        int gw = blockIdx.x * 8 + warp;
        for (int u = gw; u < NSEG * NB; u += nb * 8) {
            int m = u % NSEG;
            int b = u / NSEG;
            const long long* hs = g_hs + (size_t)b * NSLOT + m * NCELL;
            const int*       hc = g_hc + (size_t)b * NSLOT + m * NCELL;
            int base = lane * 4;
            int ncl  = (lane == 31) ? 5 : 4;
            long long ls[5]; int lc[5];
            long long runS = 0; int runC = 0;
            #pragma unroll
            for (int e = 0; e < 5; e++) {
                if (e < ncl) {
                    ls[e] = runS; lc[e] = runC;
                    runS += __ldcg(hs + base + e);
                    runC += __ldcg(hc + base + e);
                }
            }
            long long incS = runS; int incC = runC;
            #pragma unroll
            for (int off = 1; off < 32; off <<= 1) {
                long long vS = __shfl_up_sync(0xffffffffu, incS, off);
                int       vC = __shfl_up_sync(0xffffffffu, incC, off);
                if (lane >= off) { incS += vS; incC += vC; }
            }
            long long exS = incS - runS; int exC = incC - runC;
            #pragma unroll
            for (int e = 0; e < 5; e++) {
                if (e < ncl) {
                    sm.pool.ps[warp][base + e] = exS + ls[e];
                    sm.pool.pc[warp][base + e] = exC + lc[e];
                }
            }
            if (lane == 31) { sm.pool.ps[warp][NCELL] = incS; sm.pool.pc[warp][NCELL] = incC; }
            __syncwarp();

            #pragma unroll
            for (int ff = 0; ff < 4; ff++) {
                int f = lane + 32 * ff;
                int idx = m * P2 + f;
                float a = g_A[idx], c = g_Cc[idx];
                int2 rg = g_range[idx];
                long long ds = sm.pool.ps[warp][rg.y] - sm.pool.ps[warp][rg.x];
                int       dc = sm.pool.pc[warp][rg.y] - sm.pool.pc[warp][rg.x];
                float val = a * (float)((double)ds * INV_SCALE) + c * (float)dc;
                long long q = llrint((double)val * PSCALE);
                atomicAdd((unsigned long long*)&g_poolq[b * P2 + f],
                          (unsigned long long)q);
            }
            __syncwarp();
        }
    }
    grid_barrier(&g_bar[2], (unsigned)nb);

    // ---------------- Phase 3: head MLP ----------------
    for (int b = blockIdx.x; b < NB; b += nb) {
        if (tid < P2)
            sm.head.pooled[tid] =
                (float)((double)__ldcg(&g_poolq[b * P2 + tid]) * INV_PSCALE);
        __syncthreads();
        {   // layer1: 256 outputs, K=128
            float v = b3[tid];
            #pragma unroll 16
            for (int k = 0; k < P2; k++)
                v = fmaf(sm.head.pooled[k], W3[k * R1 + tid], v);
            sm.head.r1[tid] = fmaxf(v, 0.0f);
        }
        __syncthreads();
        {   // layer2: 128 outputs, 2-way K split (K=256)
            int o = tid & 127, ch = tid >> 7;
            float v = 0.0f;
            int k0 = ch * 128;
            #pragma unroll 16
            for (int k = 0; k < 128; k++)
                v = fmaf(sm.head.r1[k0 + k], W4[(k0 + k) * R2 + o], v);
            sm.head.part[tid] = v;
        }
        __syncthreads();
        if (tid < R2)
            sm.head.r2[tid] = fmaxf(b4[tid] + sm.head.part[tid] + sm.head.part[tid + 128], 0.0f);
        __syncthreads();
        {   // layer3: 64 outputs, 4-way K split (K=128)
            int o = tid & 63, ch = tid >> 6;
            float v = 0.0f;
            int k0 = ch * 32;
            #pragma unroll
            for (int k = 0; k < 32; k++)
                v = fmaf(sm.head.r2[k0 + k], W5[(k0 + k) * OD + o], v);
            sm.head.part[tid] = v;
        }
        __syncthreads();
        if (tid < OD) {
            out[b * OD + tid] = b5[tid] + sm.head.part[tid] + sm.head.part[tid + 64]
                              + sm.head.part[tid + 128] + sm.head.part[tid + 192];
        }
        __syncthreads();
    }
}

// ---------------------------------------------------------------------------
extern "C" void kernel_launch(void* const* d_in, const int* in_sizes, int n_in,
                              void* d_out, int out_size) {
    const float* dm      = (const float*)d_in[0];
    const int*   lengths = (const int*)  d_in[1];
    const float* W1 = (const float*)d_in[2],  *b1 = (const float*)d_in[3];
    const float* W2 = (const float*)d_in[4],  *b2 = (const float*)d_in[5];
    const float* W3 = (const float*)d_in[6],  *b3 = (const float*)d_in[7];
    const float* W4 = (const float*)d_in[8],  *b4 = (const float*)d_in[9];
    const float* W5 = (const float*)d_in[10], *b5 = (const float*)d_in[11];
    float* out = (float*)d_out;

    // Size grid for guaranteed co-residency (grid barriers need all blocks live).
    int dev = 0;  cudaGetDevice(&dev);
    int sms = 0;  cudaDeviceGetAttribute(&sms, cudaDevAttrMultiProcessorCount, dev);
    int maxb = 0;
    cudaOccupancyMaxActiveBlocksPerMultiprocessor(&maxb, mega_kernel, 256, 0);
    int grid = sms * maxb;
    if (grid > GRID_MAX) grid = GRID_MAX;
    if (grid < 1) grid = 1;

    mega_kernel<<<grid, 256>>>(dm, lengths, W1, b1, W2, b2,
                               W3, b3, W4, b4, W5, b5, out, grid);
}